// round 17
// baseline (speedup 1.0000x reference)
#include <cuda_runtime.h>
#include <cuda_fp16.h>
#include <cstdint>
#include <stdint.h>
#include <math.h>

#define Dm 1024
#define Fm 4096
#define Em 8
#define Tm 4096

#define BM 128
#define BN 128
#define BK 32
#define AST (BK + 8)   // 40 halfs = 80B rows -> conflict-free ldmatrix, 16B-aligned
#define BST (BK + 8)
#define STAGE_H (BM * AST)              // halfs per A (or B) stage = 5120
#define SMEM_DYN (6 * STAGE_H * 2)      // 3 stages x (A+B) = 61440 bytes

// ---- scratch (device globals; allocation is forbidden) ----
// fixed per-expert regions: expert e owns rows [e*Tm, e*Tm + g_cnt[e])
__device__ __half g_W1h[(size_t)Em * Fm * Dm];      // W1 transposed fp16: [e][f][d]
__device__ __half g_W2h[(size_t)Em * Dm * Fm];      // W2 transposed fp16: [e][d][f]
__device__ __half g_Xg[(size_t)Em * Tm * Dm];       // gathered tokens fp16 (per-expert regions)
__device__ __half g_H [(size_t)Em * Tm * Fm];       // GELU activations fp16
__device__ float  g_Y [(size_t)Em * Tm * Dm];       // expert outputs fp32
__device__ int   g_cnt[Em];                         // zero-init; re-armed by combine tail
__device__ int   g_te[Tm];            // e0 | e1<<8
__device__ int   g_tslot[2 * Tm];     // absolute slot of (token, k)
__device__ float g_tw[2 * Tm];        // routing weights

// ---- fused router: coalesced Wr loads -> top2 -> softmax -> gather ----
__global__ __launch_bounds__(256) void route_gather_kernel(const float* __restrict__ x,
                                                           const float* __restrict__ Wr,
                                                           const float* __restrict__ br) {
    int t = blockIdx.x;
    int tid = threadIdx.x;
    __shared__ __align__(16) float xrow[Dm];
    __shared__ float red[8][2][4];             // [warp][parity][expert-in-group]
    __shared__ float logits[Em];
    __shared__ int   sslot[2];

    float4 xv = ((const float4*)(x + (size_t)t * Dm))[tid];
    ((float4*)xrow)[tid] = xv;
    __syncthreads();

    float acc[4] = {0.f, 0.f, 0.f, 0.f};
    const float4* Wr4 = (const float4*)Wr;
    #pragma unroll
    for (int i = 0; i < 8; i++) {
        int idx = tid + i * 256;               // 0..2047
        float4 w = Wr4[idx];
        float xd = xrow[idx >> 1];
        acc[0] += xd * w.x; acc[1] += xd * w.y;
        acc[2] += xd * w.z; acc[3] += xd * w.w;
    }
    #pragma unroll
    for (int o = 2; o <= 16; o <<= 1) {
        #pragma unroll
        for (int k = 0; k < 4; k++) acc[k] += __shfl_xor_sync(0xffffffffu, acc[k], o);
    }
    int warp = tid >> 5, lane = tid & 31;
    if (lane < 2) {
        #pragma unroll
        for (int k = 0; k < 4; k++) red[warp][lane][k] = acc[k];
    }
    __syncthreads();
    if (tid < Em) {
        int g = tid >> 2, k = tid & 3;
        float s = br[tid];
        #pragma unroll
        for (int w = 0; w < 8; w++) s += red[w][g][k];
        logits[tid] = s;
    }
    __syncthreads();

    if (tid == 0) {
        int i0 = 0; float v0 = logits[0];
        #pragma unroll
        for (int e = 1; e < Em; e++) if (logits[e] > v0) { v0 = logits[e]; i0 = e; }
        int i1 = -1; float v1 = -1e30f;
        #pragma unroll
        for (int e = 0; e < Em; e++) if (e != i0 && logits[e] > v1) { v1 = logits[e]; i1 = e; }
        float e1 = expf(v1 - v0);
        float inv = 1.0f / (1.0f + e1);
        int s0 = atomicAdd(&g_cnt[i0], 1);
        int s1 = atomicAdd(&g_cnt[i1], 1);
        int a0 = i0 * Tm + s0, a1 = i1 * Tm + s1;
        sslot[0] = a0; sslot[1] = a1;
        g_te[t] = i0 | (i1 << 8);
        g_tslot[2 * t] = a0; g_tslot[2 * t + 1] = a1;
        g_tw[2 * t] = inv;   g_tw[2 * t + 1] = e1 * inv;
    }
    __syncthreads();

    int a0 = sslot[0], a1 = sslot[1];
    float4 v = ((const float4*)xrow)[tid];
    __half2 h0 = __floats2half2_rn(v.x, v.y);
    __half2 h1 = __floats2half2_rn(v.z, v.w);
    uint2 u;
    u.x = *(unsigned*)&h0;
    u.y = *(unsigned*)&h1;
    *(uint2*)(g_Xg + (size_t)a0 * Dm + tid * 4) = u;
    *(uint2*)(g_Xg + (size_t)a1 * Dm + tid * 4) = u;
}

// ---------------- weight convert + transpose: [e][K][N] f32 -> [e][N][K] f16 ----------------
template <int K, int N, bool IS_W1>
__global__ __launch_bounds__(256) void convert_w_kernel(const float* __restrict__ W) {
    __shared__ float tile[32][65];
    int e = blockIdx.z;
    int n0 = blockIdx.x * 64, k0 = blockIdx.y * 32;
    const float* src = W + (size_t)e * K * N;                   // [K][N]
    __half* dst = (IS_W1 ? g_W1h : g_W2h) + (size_t)e * K * N;  // [N][K]
    int tid = threadIdx.x;

    #pragma unroll
    for (int it = 0; it < 2; it++) {
        int idx = it * 256 + tid;
        int kl = idx >> 4, n4 = idx & 15;
        float4 v = *(const float4*)(src + (size_t)(k0 + kl) * N + n0 + n4 * 4);
        tile[kl][n4 * 4 + 0] = v.x;
        tile[kl][n4 * 4 + 1] = v.y;
        tile[kl][n4 * 4 + 2] = v.z;
        tile[kl][n4 * 4 + 3] = v.w;
    }
    __syncthreads();

    {
        int nl = tid >> 2, p = tid & 3;     // 64 rows x 4 chunks
        __half h[8];
        #pragma unroll
        for (int i = 0; i < 8; i++) h[i] = __float2half_rn(tile[p * 8 + i][nl]);
        *(float4*)(dst + (size_t)(n0 + nl) * K + k0 + p * 8) = *(float4*)h;
    }
}

// ---------------- fp16 mma.sync grouped GEMM (ldmatrix, 3-stage pipeline) ----------------
#define MMA_F16(d, a, b)                                                      \
    asm volatile(                                                             \
        "mma.sync.aligned.m16n8k16.row.col.f32.f16.f16.f32 "                  \
        "{%0,%1,%2,%3}, {%4,%5,%6,%7}, {%8,%9}, {%0,%1,%2,%3};"               \
        : "+f"(d[0]), "+f"(d[1]), "+f"(d[2]), "+f"(d[3])                      \
        : "r"(a[0]), "r"(a[1]), "r"(a[2]), "r"(a[3]), "r"(b[0]), "r"(b[1]))

#define LDSM4(r0, r1, r2, r3, addr)                                           \
    asm volatile("ldmatrix.sync.aligned.m8n8.x4.shared.b16 {%0,%1,%2,%3}, [%4];" \
                 : "=r"(r0), "=r"(r1), "=r"(r2), "=r"(r3) : "r"(addr))

// PHASE1: A=g_Xg (K=Dm), B=g_W1h [e][F][D], O=g_H (bias+GELU, fp16)
// PHASE2: A=g_H  (K=Fm), B=g_W2h [e][D][F], O=g_Y (raw fp32)
// eBase: first expert of this launch (grid.z covers 4 experts -> 2-stream packing)
template <bool PHASE1>
__global__ __launch_bounds__(256, 2) void gemm_kernel(const float* __restrict__ bias,
                                                      int eBase) {
    const int K   = PHASE1 ? Dm : Fm;
    const int Nt  = PHASE1 ? Fm : Dm;
    const int KT  = K / BK;

    int e = eBase + blockIdx.z;
    int cnt = g_cnt[e];
    int mBase = blockIdx.y * BM;
    if (mBase >= cnt) return;
    int off = e * Tm;
    int nBase = blockIdx.x * BN;

    const __half* A  = (PHASE1 ? g_Xg : g_H) + (size_t)(off + mBase) * K;
    const __half* Bp = (PHASE1 ? g_W1h : g_W2h) + (size_t)e * (size_t)K * (size_t)Nt
                       + (size_t)nBase * K;   // rows = n, cols = k

    extern __shared__ __half dyn[];           // [3 A stages][3 B stages]

    int tid = threadIdx.x;
    int wid = tid >> 5, lane = tid & 31;
    int wm = wid & 3, wn = wid >> 2;      // 4 x 2 warp grid, 32(M) x 64(N) per warp
    int r = lane >> 2, c = lane & 3;

    float acc[2][8][4];
    #pragma unroll
    for (int mi = 0; mi < 2; mi++)
        #pragma unroll
        for (int ni = 0; ni < 8; ni++)
            #pragma unroll
            for (int q = 0; q < 4; q++) acc[mi][ni][q] = 0.f;

    unsigned smb = (unsigned)__cvta_generic_to_shared(&dyn[0]);

    int q8 = lane >> 3, rr = lane & 7;
    unsigned offA = (unsigned)(((wm * 32 + (q8 & 1) * 8 + rr) * AST + (q8 >> 1) * 8) * 2);
    unsigned offB = (unsigned)(((wn * 64 + (q8 >> 1) * 8 + rr) * BST + (q8 & 1) * 8) * 2);

    auto load_stage = [&](int ktIdx, int buf) {
        int k0 = ktIdx * BK;
        unsigned asx = smb + (unsigned)buf * (STAGE_H * 2);
        unsigned bsx = smb + (unsigned)(3 + buf) * (STAGE_H * 2);
        #pragma unroll
        for (int i = 0; i < 2; i++) {
            int ch = tid + i * 256;
            int row = ch >> 2, kc = (ch & 3) * 8;
            const __half* src = A + (size_t)row * K + k0 + kc;
            unsigned dst = asx + (unsigned)(row * AST + kc) * 2u;
            asm volatile("cp.async.cg.shared.global [%0], [%1], 16;" :: "r"(dst), "l"(src));
        }
        #pragma unroll
        for (int i = 0; i < 2; i++) {
            int ch = tid + i * 256;
            int row = ch >> 2, kc = (ch & 3) * 8;
            const __half* src = Bp + (size_t)row * K + k0 + kc;
            unsigned dst = bsx + (unsigned)(row * BST + kc) * 2u;
            asm volatile("cp.async.cg.shared.global [%0], [%1], 16;" :: "r"(dst), "l"(src));
        }
        asm volatile("cp.async.commit_group;");
    };

    load_stage(0, 0);
    load_stage(1, 1);

    int cur = 0;
    for (int kt = 0; kt < KT; ++kt) {
        if (kt + 1 < KT) asm volatile("cp.async.wait_group 1;");
        else             asm volatile("cp.async.wait_group 0;");
        __syncthreads();
        if (kt + 2 < KT) {
            int nb = cur + 2; if (nb >= 3) nb -= 3;
            load_stage(kt + 2, nb);
        }

        unsigned aS = smb + (unsigned)cur * (STAGE_H * 2) + offA;
        unsigned bS = smb + (unsigned)(3 + cur) * (STAGE_H * 2) + offB;

        #pragma unroll
        for (int ks = 0; ks < 2; ++ks) {
            unsigned kkb = (unsigned)(ks * 16 * 2);
            unsigned a[2][4];
            LDSM4(a[0][0], a[0][1], a[0][2], a[0][3], aS + kkb);
            LDSM4(a[1][0], a[1][1], a[1][2], a[1][3], aS + kkb + 16u * AST * 2u);
            unsigned b[8][2];
            #pragma unroll
            for (int g = 0; g < 4; ++g) {
                LDSM4(b[2 * g][0], b[2 * g][1], b[2 * g + 1][0], b[2 * g + 1][1],
                      bS + kkb + (unsigned)g * 16u * BST * 2u);
            }
            #pragma unroll
            for (int mi = 0; mi < 2; ++mi)
                #pragma unroll
                for (int ni = 0; ni < 8; ++ni)
                    MMA_F16(acc[mi][ni], a[mi], b[ni]);
        }
        ++cur; if (cur == 3) cur = 0;
    }

    // ---- epilogue ----
    #pragma unroll
    for (int mi = 0; mi < 2; ++mi) {
        #pragma unroll
        for (int hh = 0; hh < 2; ++hh) {
            int m = wm * 32 + mi * 16 + r + hh * 8;
            if (mBase + m < cnt) {
                size_t slot = (size_t)(off + mBase + m);
                #pragma unroll
                for (int ni = 0; ni < 8; ++ni) {
                    int col = wn * 64 + ni * 8 + 2 * c;
                    float v0 = acc[mi][ni][hh * 2 + 0];
                    float v1 = acc[mi][ni][hh * 2 + 1];
                    if (PHASE1) {
                        v0 += bias[(size_t)e * Fm + nBase + col];
                        v1 += bias[(size_t)e * Fm + nBase + col + 1];
                        v0 = 0.5f * v0 * (1.0f + erff(v0 * 0.70710678118654752440f));
                        v1 = 0.5f * v1 * (1.0f + erff(v1 * 0.70710678118654752440f));
                        *(__half2*)(g_H + slot * Fm + nBase + col) = __floats2half2_rn(v0, v1);
                    } else {
                        *(float2*)(g_Y + slot * Dm + nBase + col) = make_float2(v0, v1);
                    }
                }
            }
        }
    }
}

// ---------------- combine: out[t] = sum_k w_k * (Y[slot_k] + b2[e_k]) ----------------
__global__ void combine_kernel(float* __restrict__ out,
                               const float* __restrict__ b2) {
    int t = blockIdx.x;
    int p = g_te[t];
    int e0 = p & 255, e1 = p >> 8;
    float w0 = g_tw[2 * t], w1 = g_tw[2 * t + 1];
    int s0 = g_tslot[2 * t], s1 = g_tslot[2 * t + 1];
    int d = threadIdx.x;
    float4 y0 = ((const float4*)(g_Y + (size_t)s0 * Dm))[d];
    float4 y1 = ((const float4*)(g_Y + (size_t)s1 * Dm))[d];
    float4 c0 = ((const float4*)(b2 + (size_t)e0 * Dm))[d];
    float4 c1 = ((const float4*)(b2 + (size_t)e1 * Dm))[d];
    float4 o;
    o.x = w0 * (y0.x + c0.x) + w1 * (y1.x + c1.x);
    o.y = w0 * (y0.y + c0.y) + w1 * (y1.y + c1.y);
    o.z = w0 * (y0.z + c0.z) + w1 * (y1.z + c1.z);
    o.w = w0 * (y0.w + c0.w) + w1 * (y1.w + c1.w);
    ((float4*)(out + (size_t)t * Dm))[d] = o;

    if (blockIdx.x == 0 && threadIdx.x < Em) g_cnt[threadIdx.x] = 0;
}

extern "C" void kernel_launch(void* const* d_in, const int* in_sizes, int n_in,
                              void* d_out, int out_size) {
    const float* x  = (const float*)d_in[0];
    const float* Wr = (const float*)d_in[1];
    const float* br = (const float*)d_in[2];
    const float* W1 = (const float*)d_in[3];
    const float* b1 = (const float*)d_in[4];
    const float* W2 = (const float*)d_in[5];
    const float* b2 = (const float*)d_in[6];
    float* out = (float*)d_out;

    cudaFuncSetAttribute(gemm_kernel<true>,  cudaFuncAttributeMaxDynamicSharedMemorySize, SMEM_DYN);
    cudaFuncSetAttribute(gemm_kernel<false>, cudaFuncAttributeMaxDynamicSharedMemorySize, SMEM_DYN);

    // Streams + events (created once on first, uncaptured, call).
    static cudaStream_t sW = nullptr, sC = nullptr;
    static cudaEvent_t evFork = nullptr, evW1 = nullptr, evW2 = nullptr;
    static cudaEvent_t evRoute = nullptr, evB = nullptr;
    static bool streamOk = false;
    if (!sW) {
        streamOk =
            cudaStreamCreateWithFlags(&sW, cudaStreamNonBlocking) == cudaSuccess &&
            cudaStreamCreateWithFlags(&sC, cudaStreamNonBlocking) == cudaSuccess &&
            cudaEventCreateWithFlags(&evFork,  cudaEventDisableTiming) == cudaSuccess &&
            cudaEventCreateWithFlags(&evW1,    cudaEventDisableTiming) == cudaSuccess &&
            cudaEventCreateWithFlags(&evW2,    cudaEventDisableTiming) == cudaSuccess &&
            cudaEventCreateWithFlags(&evRoute, cudaEventDisableTiming) == cudaSuccess &&
            cudaEventCreateWithFlags(&evB,     cudaEventDisableTiming) == cudaSuccess;
    }

    dim3 gW1(Fm / 64, Dm / 32, Em);
    dim3 gW2(Dm / 64, Fm / 32, Em);
    dim3 g1h(Fm / BN, Tm / BM, 4);   // GEMM1, 4 experts per launch
    dim3 g2h(Dm / BN, Tm / BM, 4);   // GEMM2, 4 experts per launch

    if (streamOk) {
        cudaEventRecord(evFork, 0);
        cudaStreamWaitEvent(sW, evFork, 0);
        convert_w_kernel<Dm, Fm, true ><<<gW1, 256, 0, sW>>>(W1);
        cudaEventRecord(evW1, sW);
        convert_w_kernel<Fm, Dm, false><<<gW2, 256, 0, sW>>>(W2);
        cudaEventRecord(evW2, sW);

        route_gather_kernel<<<Tm, 256>>>(x, Wr, br);
        cudaEventRecord(evRoute, 0);

        // half B chain on sC: G1(e4-7) -> G2(e4-7)
        cudaStreamWaitEvent(sC, evRoute, 0);
        cudaStreamWaitEvent(sC, evW1, 0);
        gemm_kernel<true><<<g1h, 256, SMEM_DYN, sC>>>(b1, 4);
        cudaStreamWaitEvent(sC, evW2, 0);
        gemm_kernel<false><<<g2h, 256, SMEM_DYN, sC>>>(b2, 4);
        cudaEventRecord(evB, sC);

        // half A chain on default: G1(e0-3) -> G2(e0-3)
        cudaStreamWaitEvent(0, evW1, 0);
        gemm_kernel<true><<<g1h, 256, SMEM_DYN>>>(b1, 0);
        cudaStreamWaitEvent(0, evW2, 0);
        gemm_kernel<false><<<g2h, 256, SMEM_DYN>>>(b2, 0);

        cudaStreamWaitEvent(0, evB, 0);
        combine_kernel<<<Tm, 256>>>(out, b2);
    } else {
        convert_w_kernel<Dm, Fm, true ><<<gW1, 256>>>(W1);
        convert_w_kernel<Fm, Dm, false><<<gW2, 256>>>(W2);
        route_gather_kernel<<<Tm, 256>>>(x, Wr, br);
        gemm_kernel<true><<<g1h, 256, SMEM_DYN>>>(b1, 0);
        gemm_kernel<true><<<g1h, 256, SMEM_DYN>>>(b1, 4);
        gemm_kernel<false><<<g2h, 256, SMEM_DYN>>>(b2, 0);
        gemm_kernel<false><<<g2h, 256, SMEM_DYN>>>(b2, 4);
        combine_kernel<<<Tm, 256>>>(out, b2);
    }
}